// round 3
// baseline (speedup 1.0000x reference)
#include <cuda_runtime.h>

// NLSearch: vid0, vid1 (1,3,32,256,256) f32. Query grid 64x64 stride 4,
// patch 7x7, shift window 8x8 (offsets -4..3), K=7.
// Output float32: [0,86016) dists (1,1,12288,7); [86016,344064) inds (..,7,3).

typedef unsigned long long u64;

#define V1_RSTR 16    // row stride (floats), 64B -> LDS.128 aligned
#define V1_CSTR 228   // 14*16=224 padded to 228: /4=57 odd -> conflict-free .128
#define V0_RSTR 8
#define V0_CSTR 60    // 7*8=56 padded to 60: /4=15 odd -> conflict-free .128

__device__ __forceinline__ int refl(int x) {
    x = x < 0 ? -x : x;
    return x > 255 ? 510 - x : x;
}

__device__ __forceinline__ u64 pack2(float lo, float hi) {
    u64 d; asm("mov.b64 %0, {%1, %2};" : "=l"(d) : "f"(lo), "f"(hi)); return d;
}
__device__ __forceinline__ u64 fma2(u64 a, u64 b, u64 c) {
    u64 d; asm("fma.rn.f32x2 %0, %1, %2, %3;" : "=l"(d) : "l"(a), "l"(b), "l"(c)); return d;
}
__device__ __forceinline__ u64 add2(u64 a, u64 b) {
    u64 d; asm("add.rn.f32x2 %0, %1, %2;" : "=l"(d) : "l"(a), "l"(b)); return d;
}
__device__ __forceinline__ void unpack2(u64 v, float& lo, float& hi) {
    asm("mov.b64 {%0, %1}, %2;" : "=f"(lo), "=f"(hi) : "l"(v));
}

__global__ void __launch_bounds__(256, 3)
nls_kernel(const float* __restrict__ vid0,
           const float* __restrict__ vid1,
           float* __restrict__ out)
{
    __shared__ __align__(16) float v1s[32 * V1_CSTR];
    __shared__ __align__(16) float v0s[32 * V0_CSTR];
    __shared__ float sdist[64];

    const int b = blockIdx.x;
    const int t = b >> 12;
    const int r = b & 4095;
    const int n = r >> 6;
    const int v = r & 63;
    const int qh = n << 2;
    const int qw = v << 2;

    const int tid  = threadIdx.x;
    const int lane = tid & 31;
    const int w    = tid >> 5;       // warp id = s0 index (s0 = w - 4)

    // ---- stage (reflect applied); thread->(element) fixed, loop channels ----
    if (tid < 196) {
        int rr = tid / 14;
        int cc = tid - rr * 14;
        int hg = refl(qh - 7 + rr);
        int wg = refl(qw - 7 + cc);
        const float* src = vid1 + (size_t)t * 32 * 65536 + (hg << 8) + wg;
        float* dst = v1s + rr * V1_RSTR + cc;
#pragma unroll 8
        for (int c = 0; c < 32; c++)
            dst[c * V1_CSTR] = src[c << 16];
    } else if (tid < 196 + 49) {
        int idx = tid - 196;
        int ii = idx / 7;
        int jj = idx - ii * 7;
        int hg = refl(qh - 3 + ii);
        int wg = refl(qw - 3 + jj);
        const float* src = vid0 + (size_t)t * 32 * 65536 + (hg << 8) + wg;
        float* dst = v0s + ii * V0_RSTR + jj;
#pragma unroll 8
        for (int c = 0; c < 32; c++)
            dst[c * V0_CSTR] = src[c << 16];
    }
    __syncthreads();

    // ---- compute: warp w = shift row s0; lane = channel; loop i = patch row.
    // acc[s1] += v0[c][i][j] * v1[c][w+i][j+s1]; accs packed in f32x2 pairs.
    const float* a_base = v0s + lane * V0_CSTR;
    const float* b_base = v1s + lane * V1_CSTR + w * V1_RSTR;

    u64 P[4];
#pragma unroll
    for (int m = 0; m < 4; m++) P[m] = 0ull;

#pragma unroll
    for (int i = 0; i < 7; i++) {
        const float4* br = (const float4*)(b_base + i * V1_RSTR);
        float4 b0 = br[0], b1 = br[1], b2 = br[2], b3 = br[3];
        const float4* ar = (const float4*)(a_base + i * V0_RSTR);
        float4 a0 = ar[0], a1 = ar[1];

        u64 E[7], O[6];
        E[0] = pack2(b0.x, b0.y); E[1] = pack2(b0.z, b0.w);
        E[2] = pack2(b1.x, b1.y); E[3] = pack2(b1.z, b1.w);
        E[4] = pack2(b2.x, b2.y); E[5] = pack2(b2.z, b2.w);
        E[6] = pack2(b3.x, b3.y);
        O[0] = pack2(b0.y, b0.z); O[1] = pack2(b0.w, b1.x);
        O[2] = pack2(b1.y, b1.z); O[3] = pack2(b1.w, b2.x);
        O[4] = pack2(b2.y, b2.z); O[5] = pack2(b2.w, b3.x);

        float a[7] = {a0.x, a0.y, a0.z, a0.w, a1.x, a1.y, a1.z};

#pragma unroll
        for (int j = 0; j < 7; j++) {
            u64 AA = pack2(a[j], a[j]);
#pragma unroll
            for (int m = 0; m < 4; m++) {
                u64 bp = (j & 1) ? O[((j - 1) >> 1) + m] : E[(j >> 1) + m];
                P[m] = fma2(AA, bp, P[m]);
            }
        }
    }

    // ---- warp-reduce 4 packed accs over the 32 channels ----
#pragma unroll
    for (int m = 0; m < 4; m++) {
        u64 val = P[m];
#pragma unroll
        for (int o = 16; o > 0; o >>= 1)
            val = add2(val, __shfl_xor_sync(0xffffffffu, val, o));
        if (lane == 0) {
            float lo, hi;
            unpack2(val, lo, hi);
            sdist[(w << 3) + 2 * m]     = lo;
            sdist[(w << 3) + 2 * m + 1] = hi;
        }
    }
    __syncthreads();

    // ---- top-7 (warp 0): value desc, index asc tie-break ----
    if (w == 0) {
        float a0 = sdist[lane];
        float a1 = sdist[lane + 32];
        if (lane == 4) a1 += 1e30f;   // self shift idx 36 boosted for selection

        const int q = t * 4096 + n * 64 + v;
        float* dbase = out + (size_t)q * 7;
        float* ibase = out + 86016 + (size_t)q * 21;

#pragma unroll
        for (int k = 0; k < 7; k++) {
            float bv = (a0 >= a1) ? a0 : a1;
            int   bi = (a0 >= a1) ? lane : lane + 32;
#pragma unroll
            for (int o = 16; o > 0; o >>= 1) {
                float ov = __shfl_xor_sync(0xffffffffu, bv, o);
                int   oi = __shfl_xor_sync(0xffffffffu, bi, o);
                if (ov > bv || (ov == bv && oi < bi)) { bv = ov; bi = oi; }
            }
            if (bi == lane)      a0 = -3.4e38f;
            if (bi == lane + 32) a1 = -3.4e38f;
            if (lane == 0) {
                dbase[k] = sdist[bi];
                int s0 = bi >> 3;
                int s1 = bi & 7;
                ibase[k * 3 + 0] = (float)t;
                ibase[k * 3 + 1] = (float)refl(qh + s0 - 4);
                ibase[k * 3 + 2] = (float)refl(qw + s1 - 4);
            }
        }
    }
}

extern "C" void kernel_launch(void* const* d_in, const int* in_sizes, int n_in,
                              void* d_out, int out_size)
{
    const float* vid0 = (const float*)d_in[0];
    const float* vid1 = (const float*)d_in[1];
    float* out = (float*)d_out;
    nls_kernel<<<12288, 256>>>(vid0, vid1, out);
}